// round 16
// baseline (speedup 1.0000x reference)
#include <cuda_runtime.h>
#include <cuda_bf16.h>

// SimSiam loss, algebraically reduced:
//   loss = -0.5 * sum_c( P_c . Z_c  -  sum_{i in c} pn_i.zn_i ) / npairs
// with npairs = sum_c m_c*(m_c-1)/2.
//
// GATHER v2, single launch: one block per GROUP of 4 classes (128 blocks).
// Each block scans targets with vectorized loads (scan traffic 8MB vs 32MB
// in v1), collects matches via warp-ballot into a ushort-packed smem list,
// gathers+normalizes rows with per-warp REGISTER accumulators for its 4
// classes (no atomics in the hot loop), combines warp partials through one
// smem buffer in two passes, and computes dots/diag/pairs locally.
// Epilogue: one spread atomic per block; last-done block reduces 64 slots
// and restores the zero-scratch invariant.

#define NCLASS 512
#define D      128
#define EPS    1e-8f
#define CPG    4                    // classes per group/block
#define NBLK   (NCLASS / CPG)       // 128 blocks
#define MAXN   8192
#define SLOTS  64

__device__ double             g_Sslot[SLOTS];
__device__ unsigned long long g_Pslot[SLOTS];
__device__ unsigned int       g_done;

__global__ void __launch_bounds__(256)
simsiam_gather2(const float* __restrict__ ps,
                const float* __restrict__ zs,
                const void*  __restrict__ tgv,
                float* __restrict__ out,
                int n_rows) {
    __shared__ unsigned short s_list[MAXN];      // 16KB: row | (cl<<13)
    __shared__ float  sbuf[8 * CPG * D];         // 16KB: per-warp partials
    __shared__ float  sPfin[CPG * D];            // 2KB: combined P sums
    __shared__ double sdiag[8];
    __shared__ float  sdot2[8][2];
    __shared__ int    s_m, s_mc[CPG], s_is64, s_last;
    __shared__ double sv1; __shared__ unsigned long long pv1;

    int tid  = threadIdx.x;
    int lane = tid & 31;
    int wid  = tid >> 5;
    int grp  = blockIdx.x;                       // classes grp*4 .. grp*4+3

    if (tid == 0) s_m = 0;
    if (tid < CPG) s_mc[tid] = 0;

    // ---- targets dtype sniff (warp 0): first 64 int64-view slots (512 B,
    // in-bounds for either dtype; misdetect prob ~2^-576 for random labels).
    if (wid == 0) {
        const long long* t64 = (const long long*)tgv;
        int nslots = n_rows / 2;
        int k = (nslots < 64) ? nslots : 64;
        int bad = 0;
        for (int i = lane; i < k; i += 32) {
            long long v = __ldg(&t64[i]);
            if (v < 0 || v >= NCLASS) bad = 1;
        }
        bad = __any_sync(0xFFFFFFFFu, bad);
        if (lane == 0) s_is64 = !bad;
    }
    __syncthreads();
    int is64 = s_is64;

    // ---- phase A: vectorized scan; ballot insert (1 smem atomic/warp/hit)
    auto insert = [&](int match, int row, int cl) {
        unsigned mask = __ballot_sync(0xFFFFFFFFu, match);
        if (mask) {
            int leader = __ffs(mask) - 1;
            int base = 0;
            if (lane == leader) base = atomicAdd(&s_m, __popc(mask));
            base = __shfl_sync(0xFFFFFFFFu, base, leader);
            if (match) {
                int pos = base + __popc(mask & ((1u << lane) - 1u));
                s_list[pos] = (unsigned short)(row | (cl << 13));
                atomicAdd(&s_mc[cl], 1);
            }
        }
    };

    if (is64) {
        const longlong2* t2 = (const longlong2*)tgv;
        int nv = n_rows >> 1;                    // 2 labels per 16B load
        for (int v = tid; v < nv; v += 256) {
            longlong2 q = __ldg(&t2[v]);
            int t0 = (int)q.x, t1 = (int)q.y;
            insert((t0 >> 2) == grp, 2 * v,     t0 & 3);
            insert((t1 >> 2) == grp, 2 * v + 1, t1 & 3);
        }
    } else {
        const int4* t4 = (const int4*)tgv;
        int nv = n_rows >> 2;                    // 4 labels per 16B load
        for (int v = tid; v < nv; v += 256) {
            int4 q = __ldg(&t4[v]);
            insert((q.x >> 2) == grp, 4 * v,     q.x & 3);
            insert((q.y >> 2) == grp, 4 * v + 1, q.y & 3);
            insert((q.z >> 2) == grp, 4 * v + 2, q.z & 3);
            insert((q.w >> 2) == grp, 4 * v + 3, q.w & 3);
        }
    }
    __syncthreads();
    int m = s_m;

    // ---- phase B: warp k handles list entries k, k+8, ... ----
    float4 zero4 = make_float4(0.f, 0.f, 0.f, 0.f);
    float4 P0 = zero4, P1 = zero4, P2 = zero4, P3 = zero4;
    float4 Z0 = zero4, Z1 = zero4, Z2 = zero4, Z3 = zero4;
    double dacc = 0.0;

    for (int k = wid; k < m; k += 8) {
        int e   = s_list[k];
        int row = e & 0x1FFF;
        int cl  = e >> 13;

        float4 a = reinterpret_cast<const float4*>(ps)[row * (D / 4) + lane];
        float4 b = reinterpret_cast<const float4*>(zs)[row * (D / 4) + lane];

        float sa = a.x * a.x + a.y * a.y + a.z * a.z + a.w * a.w;
        float sb = b.x * b.x + b.y * b.y + b.z * b.z + b.w * b.w;
        float dp = a.x * b.x + a.y * b.y + a.z * b.z + a.w * b.w;

        #pragma unroll
        for (int o = 16; o > 0; o >>= 1) {
            sa += __shfl_xor_sync(0xFFFFFFFFu, sa, o);
            sb += __shfl_xor_sync(0xFFFFFFFFu, sb, o);
            dp += __shfl_xor_sync(0xFFFFFFFFu, dp, o);
        }

        float invp = 1.0f / fmaxf(sqrtf(sa), EPS);
        float invz = 1.0f / fmaxf(sqrtf(sb), EPS);

        float4 na = make_float4(a.x * invp, a.y * invp, a.z * invp, a.w * invp);
        float4 nb = make_float4(b.x * invz, b.y * invz, b.z * invz, b.w * invz);

        if (cl == 0)      { P0.x+=na.x; P0.y+=na.y; P0.z+=na.z; P0.w+=na.w;
                            Z0.x+=nb.x; Z0.y+=nb.y; Z0.z+=nb.z; Z0.w+=nb.w; }
        else if (cl == 1) { P1.x+=na.x; P1.y+=na.y; P1.z+=na.z; P1.w+=na.w;
                            Z1.x+=nb.x; Z1.y+=nb.y; Z1.z+=nb.z; Z1.w+=nb.w; }
        else if (cl == 2) { P2.x+=na.x; P2.y+=na.y; P2.z+=na.z; P2.w+=na.w;
                            Z2.x+=nb.x; Z2.y+=nb.y; Z2.z+=nb.z; Z2.w+=nb.w; }
        else              { P3.x+=na.x; P3.y+=na.y; P3.z+=na.z; P3.w+=na.w;
                            Z3.x+=nb.x; Z3.y+=nb.y; Z3.z+=nb.z; Z3.w+=nb.w; }

        if (lane == 0) dacc += (double)(dp * invp * invz);
    }
    if (lane == 0) sdiag[wid] = dacc;

    // ---- pass 1: combine P across warps ----
    {
        float4* wb = reinterpret_cast<float4*>(&sbuf[wid * (CPG * D)]);
        wb[0 * 32 + lane] = P0;
        wb[1 * 32 + lane] = P1;
        wb[2 * 32 + lane] = P2;
        wb[3 * 32 + lane] = P3;
    }
    __syncthreads();
    for (int pair = tid; pair < CPG * D; pair += 256) {
        float s = 0.f;
        #pragma unroll
        for (int w = 0; w < 8; w++) s += sbuf[w * (CPG * D) + pair];
        sPfin[pair] = s;
    }
    __syncthreads();

    // ---- pass 2: combine Z, form products, per-class reduce ----
    {
        float4* wb = reinterpret_cast<float4*>(&sbuf[wid * (CPG * D)]);
        wb[0 * 32 + lane] = Z0;
        wb[1 * 32 + lane] = Z1;
        wb[2 * 32 + lane] = Z2;
        wb[3 * 32 + lane] = Z3;
    }
    __syncthreads();

    float prod0, prod1;
    {
        int pair = tid;                         // classes 0/1
        float sz = 0.f;
        #pragma unroll
        for (int w = 0; w < 8; w++) sz += sbuf[w * (CPG * D) + pair];
        prod0 = sPfin[pair] * sz;

        pair = tid + 256;                       // classes 2/3
        sz = 0.f;
        #pragma unroll
        for (int w = 0; w < 8; w++) sz += sbuf[w * (CPG * D) + pair];
        prod1 = sPfin[pair] * sz;
    }
    #pragma unroll
    for (int o = 16; o > 0; o >>= 1) {
        prod0 += __shfl_xor_sync(0xFFFFFFFFu, prod0, o);
        prod1 += __shfl_xor_sync(0xFFFFFFFFu, prod1, o);
    }
    if (lane == 0) { sdot2[wid][0] = prod0; sdot2[wid][1] = prod1; }
    __syncthreads();

    // ---- block epilogue ----
    if (tid == 0) {
        double dot = 0.0;
        #pragma unroll
        for (int w = 0; w < 8; w++)
            dot += (double)sdot2[w][0] + (double)sdot2[w][1];
        double dg = sdiag[0] + sdiag[1] + sdiag[2] + sdiag[3]
                  + sdiag[4] + sdiag[5] + sdiag[6] + sdiag[7];
        unsigned long long pr = 0ull;
        #pragma unroll
        for (int c = 0; c < CPG; c++) {
            unsigned long long mm = (unsigned long long)s_mc[c];
            pr += mm * (mm - 1ull) / 2ull;
        }
        atomicAdd(&g_Sslot[grp & (SLOTS - 1)], dot - dg);
        if (pr) atomicAdd(&g_Pslot[grp & (SLOTS - 1)], pr);
        __threadfence();
        unsigned int done = atomicAdd(&g_done, 1u);
        s_last = (done == (unsigned int)(NBLK - 1));
    }
    __syncthreads();

    // ---- last-done block: reduce the 64 slots, emit loss, re-zero ----
    if (s_last) {
        __threadfence();
        double             sv = 0.0;
        unsigned long long pv = 0ull;
        if (tid < SLOTS) {
            sv = g_Sslot[tid];
            pv = g_Pslot[tid];
            g_Sslot[tid] = 0.0;
            g_Pslot[tid] = 0ull;
        }
        #pragma unroll
        for (int o = 16; o > 0; o >>= 1) {
            sv += __shfl_xor_sync(0xFFFFFFFFu, sv, o);
            pv += __shfl_xor_sync(0xFFFFFFFFu, pv, o);
        }
        if (tid == 32) { sv1 = sv; pv1 = pv; }
        __syncthreads();
        if (tid == 0) {
            double S  = sv + sv1;
            unsigned long long pr = pv + pv1;
            double np = (pr > 0ull) ? (double)pr : 1.0;
            out[0] = (float)(-0.5 * S / np);
            g_done = 0u;
        }
    }
}

// ---------------------------------------------------------------------------
extern "C" void kernel_launch(void* const* d_in, const int* in_sizes, int n_in,
                              void* d_out, int out_size) {
    const float* ps  = (const float*)d_in[0];
    const float* zs  = (const float*)d_in[1];
    const void*  tgt = d_in[2];
    float*       out = (float*)d_out;

    int n_rows = in_sizes[0] / D;   // 8192

    simsiam_gather2<<<NBLK, 256>>>(ps, zs, tgt, out, n_rows);
}

// round 17
// speedup vs baseline: 1.2918x; 1.2918x over previous
#include <cuda_runtime.h>
#include <cuda_bf16.h>

// SimSiam loss, algebraically reduced:
//   loss = -0.5 * sum_c( P_c . Z_c  -  sum_{i in c} pn_i.zn_i ) / npairs
// with npairs = sum_c m_c*(m_c-1)/2.
//
// COUNTING-SORT + GATHER (two kernels + PDL):
//  1. build_kernel: one thread per row writes its row index into a
//     per-class bucket (8K int atomics total — replaces the champion's
//     2M f32 atomic-adds through the L2 atomic ALUs, which were its
//     ~6-7us wall, and gather-v1's 32MB redundant target scan).
//  2. gather_kernel (PDL, one block per class): reads its bucket, gathers
//     and normalizes its ~16 rows, computes P_c.Z_c, diag and pairs
//     locally; spread-slot epilogue, last-done block emits the loss.
// CAP=96 bucket capacity: impossible to overflow for Binomial(8192,1/512)
// data; if m>CAP the class block falls back to scanning targets directly
// (correct for any input, never taken here). Counts are exact either way.
//
// Scratch invariant: g_cnt / slots / done are ZERO at kernel_launch entry
// (zero at module load; gather_kernel re-zeros). g_idx needs no zeroing —
// reads are bounded by the freshly written count.

#define NCLASS 512
#define D      128
#define EPS    1e-8f
#define CAP    96
#define SLOTS  64

__device__ int                g_cnt[NCLASS];
__device__ int                g_idx[NCLASS * CAP];
__device__ double             g_Sslot[SLOTS];
__device__ unsigned long long g_Pslot[SLOTS];
__device__ unsigned int       g_done;

// ---------------------------------------------------------------------------
// Targets dtype sniff, shared by both kernels: warp reads the first 64
// int64-view slots (512 B, in-bounds for either dtype at n=8192); an int32
// buffer misdetects only if 64 consecutive odd labels are zero (~2^-576).
__device__ __forceinline__ int sniff_is64(const void* tgv, int n_rows, int lane) {
    const long long* t64 = (const long long*)tgv;
    int nslots = n_rows / 2;
    int k = (nslots < 64) ? nslots : 64;
    int bad = 0;
    for (int i = lane; i < k; i += 32) {
        long long v = __ldg(&t64[i]);
        if (v < 0 || v >= NCLASS) bad = 1;
    }
    return !__any_sync(0xFFFFFFFFu, bad);
}

__device__ __forceinline__ int load_target(const void* tgv, int is64, int i) {
    if (is64) return (int)reinterpret_cast<const long long*>(tgv)[i];
    return reinterpret_cast<const int*>(tgv)[i];
}

// ---------------------------------------------------------------------------
// Kernel 1: counting sort. One thread per row.
__global__ void __launch_bounds__(256)
build_kernel(const void* __restrict__ tgv, int n_rows) {
    __shared__ int s_is64;
    int tid = threadIdx.x;
    if (tid < 32) {
        int is64 = sniff_is64(tgv, n_rows, tid);
        if (tid == 0) s_is64 = is64;
    }
    __syncthreads();
    int is64 = s_is64;

    int i = blockIdx.x * blockDim.x + tid;
    if (i < n_rows) {
        int t = load_target(tgv, is64, i);
        int p = atomicAdd(&g_cnt[t], 1);
        if (p < CAP) g_idx[t * CAP + p] = i;
    }
}

// ---------------------------------------------------------------------------
// Kernel 2 (PDL): one block per class. Gather rows, normalize, local sums.
__global__ void __launch_bounds__(256)
gather_kernel(const float* __restrict__ ps,
              const float* __restrict__ zs,
              const void*  __restrict__ tgv,
              float* __restrict__ out,
              int n_rows) {
    __shared__ float  sPf[D], sZf[D];
    __shared__ double sdiag[8];
    __shared__ double sdot[4];
    __shared__ int    s_is64, s_last;
    __shared__ double sv1; __shared__ unsigned long long pv1;

    int tid  = threadIdx.x;
    int lane = tid & 31;
    int wid  = tid >> 5;
    int c    = blockIdx.x;

    if (tid < D)          sPf[tid] = 0.f;
    else if (tid < 2 * D) sZf[tid - D] = 0.f;
    if (tid < 32) {
        int is64 = sniff_is64(tgv, n_rows, tid);
        if (tid == 0) s_is64 = is64;
    }

    // Wait for build_kernel's buckets (PDL dependency).
    cudaGridDependencySynchronize();
    __syncthreads();
    int is64 = s_is64;
    int m = g_cnt[c];

    float4 accP = make_float4(0.f, 0.f, 0.f, 0.f);
    float4 accZ = make_float4(0.f, 0.f, 0.f, 0.f);
    double dacc = 0.0;

    auto process_row = [&](int r) {
        float4 a = reinterpret_cast<const float4*>(ps)[r * (D / 4) + lane];
        float4 b = reinterpret_cast<const float4*>(zs)[r * (D / 4) + lane];

        float sa = a.x * a.x + a.y * a.y + a.z * a.z + a.w * a.w;
        float sb = b.x * b.x + b.y * b.y + b.z * b.z + b.w * b.w;
        float dp = a.x * b.x + a.y * b.y + a.z * b.z + a.w * b.w;

        #pragma unroll
        for (int o = 16; o > 0; o >>= 1) {
            sa += __shfl_xor_sync(0xFFFFFFFFu, sa, o);
            sb += __shfl_xor_sync(0xFFFFFFFFu, sb, o);
            dp += __shfl_xor_sync(0xFFFFFFFFu, dp, o);
        }

        float invp = 1.0f / fmaxf(sqrtf(sa), EPS);
        float invz = 1.0f / fmaxf(sqrtf(sb), EPS);

        accP.x += a.x * invp; accP.y += a.y * invp;
        accP.z += a.z * invp; accP.w += a.w * invp;
        accZ.x += b.x * invz; accZ.y += b.y * invz;
        accZ.z += b.z * invz; accZ.w += b.w * invz;
        if (lane == 0) dacc += (double)(dp * invp * invz);
    };

    if (m <= CAP) {
        for (int k = wid; k < m; k += 8)
            process_row(g_idx[c * CAP + k]);
    } else {
        // overflow fallback (unreachable for this data distribution):
        // scan all targets for class c directly.
        for (int i = wid; i < n_rows; i += 8) {
            int t;
            if (lane == 0) t = load_target(tgv, is64, i);
            t = __shfl_sync(0xFFFFFFFFu, t, 0);
            if (t == c) process_row(i);
        }
    }

    // combine warp accumulators (8-way smem atomics)
    int base = lane * 4;
    atomicAdd(&sPf[base + 0], accP.x);
    atomicAdd(&sPf[base + 1], accP.y);
    atomicAdd(&sPf[base + 2], accP.z);
    atomicAdd(&sPf[base + 3], accP.w);
    atomicAdd(&sZf[base + 0], accZ.x);
    atomicAdd(&sZf[base + 1], accZ.y);
    atomicAdd(&sZf[base + 2], accZ.z);
    atomicAdd(&sZf[base + 3], accZ.w);
    if (lane == 0) sdiag[wid] = dacc;
    __syncthreads();

    // local dot P_c . Z_c (threads 0..127)
    if (tid < D) {
        float prod = sPf[tid] * sZf[tid];
        #pragma unroll
        for (int o = 16; o > 0; o >>= 1)
            prod += __shfl_xor_sync(0xFFFFFFFFu, prod, o);
        if (lane == 0) sdot[wid] = (double)prod;
    }
    if (tid == 0) g_cnt[c] = 0;            // restore zero invariant
    __syncthreads();

    // block epilogue: one spread atomic; last-done block finishes
    if (tid == 0) {
        double dot = sdot[0] + sdot[1] + sdot[2] + sdot[3];
        double dg  = sdiag[0] + sdiag[1] + sdiag[2] + sdiag[3]
                   + sdiag[4] + sdiag[5] + sdiag[6] + sdiag[7];
        unsigned long long mm = (unsigned long long)m;
        atomicAdd(&g_Sslot[c & (SLOTS - 1)], dot - dg);
        if (mm > 1ull) atomicAdd(&g_Pslot[c & (SLOTS - 1)], mm * (mm - 1ull) / 2ull);
        __threadfence();
        unsigned int done = atomicAdd(&g_done, 1u);
        s_last = (done == (unsigned int)(NCLASS - 1));
    }
    __syncthreads();

    if (s_last) {
        __threadfence();                   // observe all blocks' slot atomics
        double             sv = 0.0;
        unsigned long long pv = 0ull;
        if (tid < SLOTS) {
            sv = g_Sslot[tid];
            pv = g_Pslot[tid];
            g_Sslot[tid] = 0.0;
            g_Pslot[tid] = 0ull;
        }
        #pragma unroll
        for (int o = 16; o > 0; o >>= 1) {
            sv += __shfl_xor_sync(0xFFFFFFFFu, sv, o);
            pv += __shfl_xor_sync(0xFFFFFFFFu, pv, o);
        }
        if (tid == 32) { sv1 = sv; pv1 = pv; }
        __syncthreads();
        if (tid == 0) {
            double S  = sv + sv1;
            unsigned long long pr = pv + pv1;
            double np = (pr > 0ull) ? (double)pr : 1.0;
            out[0] = (float)(-0.5 * S / np);
            g_done = 0u;
        }
    }
}

// ---------------------------------------------------------------------------
extern "C" void kernel_launch(void* const* d_in, const int* in_sizes, int n_in,
                              void* d_out, int out_size) {
    const float* ps  = (const float*)d_in[0];
    const float* zs  = (const float*)d_in[1];
    const void*  tgt = d_in[2];
    float*       out = (float*)d_out;

    int n_rows = in_sizes[0] / D;   // 8192

    build_kernel<<<(n_rows + 255) / 256, 256>>>(tgt, n_rows);

    // PDL: gather_kernel scheduled during build; blocks at grid sync.
    cudaLaunchConfig_t cfg = {};
    cfg.gridDim  = dim3(NCLASS, 1, 1);
    cfg.blockDim = dim3(256, 1, 1);
    cfg.dynamicSmemBytes = 0;
    cfg.stream = 0;
    cudaLaunchAttribute attrs[1];
    attrs[0].id = cudaLaunchAttributeProgrammaticStreamSerialization;
    attrs[0].val.programmaticStreamSerializationAllowed = 1;
    cfg.attrs = attrs;
    cfg.numAttrs = 1;
    cudaLaunchKernelEx(&cfg, gather_kernel, ps, zs, tgt, out, n_rows);
}